// round 2
// baseline (speedup 1.0000x reference)
#include <cuda_runtime.h>

#define BB 8
#define TTOT 100
#define NN 100000
#define MARGIN_F 0.1f
#define THRESH_F 0.5f
#define T_TILE 10
#define NSPLIT 32
#define NTHREADS 256
#define NBLOCKS (NSPLIT * (TTOT / T_TILE) * BB)

// Scratch (device globals; no allocation)
__device__ float4 g_retraj[BB * TTOT];   // (rx, ry, rz, r2)
__device__ float  g_lval[BB][3];
__device__ float  g_uval[BB][3];
__device__ float4 g_pts[BB * NN];        // (-2x, -2y, -2z, m2)
__device__ float  g_w[BB * NN];          // rad + MARGIN, or NaN if outside
__device__ int    g_acc[BB * TTOT];      // per-(b,t) max, float bits (>= 0)
__device__ unsigned int g_done;

__device__ __forceinline__ float fast_sqrt(float x) {
    float r;
    asm("sqrt.approx.f32 %0, %1;" : "=f"(r) : "f"(x));
    return r;
}

// Kernel 1: retrajs (+ r2), per-b bounds, zero accumulators + counter
__global__ void prep_kernel(const float* __restrict__ outputs,
                            const float* __restrict__ c2ws,
                            const float* __restrict__ ss) {
    int tid = threadIdx.x;
    if (tid == 0) g_done = 0;
    for (int i = tid; i < BB * TTOT; i += blockDim.x) {
        int b = i / TTOT;
        float s = ss[b];
        const float* o = outputs + i * 3;
        const float* M = c2ws + b * 16;
        float o0 = o[0], o1 = o[1], o2 = o[2];
        float r[3];
        #pragma unroll
        for (int e = 0; e < 3; e++) {
            float a0 = M[e * 4 + 0] * s;
            float a1 = M[e * 4 + 1] * s;
            float a2 = M[e * 4 + 2] * s;
            r[e] = o0 * a0 + o1 * a1 + o2 * a2 + M[e * 4 + 3];
        }
        float r2 = r[0] * r[0] + r[1] * r[1] + r[2] * r[2];
        g_retraj[i] = make_float4(r[0], r[1], r[2], r2);
        g_acc[i] = 0;
    }
    __syncthreads();
    if (tid < BB * 3) {
        int b = tid / 3, e = tid % 3;
        float thres = THRESH_F * ss[0];
        float mn = 1e30f, mx = -1e30f;
        for (int t = 0; t < TTOT; t++) {
            float4 rr = g_retraj[b * TTOT + t];
            float v = (e == 0) ? rr.x : ((e == 1) ? rr.y : rr.z);
            mn = fminf(mn, v);
            mx = fmaxf(mx, v);
        }
        g_lval[b][e] = mn - thres;
        g_uval[b][e] = mx + thres;
    }
}

// Kernel 2: per-b point table; outside -> w = NaN (kills compare for free)
__global__ void mask_kernel(const float* __restrict__ means,
                            const float* __restrict__ scales) {
    int i = blockIdx.x * blockDim.x + threadIdx.x;
    if (i >= BB * NN) return;
    int b = i / NN;
    int n = i - b * NN;
    float mx = means[n * 3 + 0];
    float my = means[n * 3 + 1];
    float mz = means[n * 3 + 2];
    float s0 = scales[n * 3 + 0];
    float s1 = scales[n * 3 + 1];
    float s2 = scales[n * 3 + 2];
    float rad = fmaxf(s0, fmaxf(s1, s2));
    bool inside = (mx >= g_lval[b][0]) & (mx <= g_uval[b][0]) &
                  (my >= g_lval[b][1]) & (my <= g_uval[b][1]) &
                  (mz >= g_lval[b][2]) & (mz <= g_uval[b][2]);
    float m2 = mx * mx + my * my + mz * mz;
    g_pts[i] = make_float4(-2.0f * mx, -2.0f * my, -2.0f * mz, m2);
    g_w[i] = inside ? (rad + MARGIN_F) : __int_as_float(0x7fffffff); // NaN
}

// Kernel 3: main — sqrt-free gated max, fused final reduction
__global__ void __launch_bounds__(NTHREADS) main_kernel(float* __restrict__ out) {
    int b  = blockIdx.z;
    int tt = blockIdx.y;
    int s  = blockIdx.x;
    int tbase = tt * T_TILE;

    float rx[T_TILE], ry[T_TILE], rz[T_TILE], C[T_TILE], acc[T_TILE];
    #pragma unroll
    for (int j = 0; j < T_TILE; j++) {
        float4 r = g_retraj[b * TTOT + tbase + j];
        rx[j] = r.x; ry[j] = r.y; rz[j] = r.z; C[j] = r.w;
        acc[j] = 0.0f;
    }

    const float4* __restrict__ pts = g_pts + (size_t)b * NN;
    const float*  __restrict__ wv  = g_w  + (size_t)b * NN;
    const int chunk = (NN + NSPLIT - 1) / NSPLIT;
    int n0 = s * chunk;
    int n1 = n0 + chunk; if (n1 > NN) n1 = NN;

    for (int n = n0 + threadIdx.x; n < n1; n += NTHREADS) {
        float4 p = pts[n];
        float  w = wv[n];
        #pragma unroll
        for (int j = 0; j < T_TILE; j++) {
            // d2 = C + m2 + (-2x)*rx + (-2y)*ry + (-2z)*rz
            float d2 = C[j] + p.w;
            d2 = fmaf(p.x, rx[j], d2);
            d2 = fmaf(p.y, ry[j], d2);
            d2 = fmaf(p.z, rz[j], d2);
            float thr = w - acc[j];          // NaN for outside points
            float q   = thr * thr;
            if (d2 < q) {                    // false if w==NaN; rare otherwise
                acc[j] = fmaxf(acc[j], w - fast_sqrt(fmaxf(d2, 0.0f)));
            }
        }
    }

    // Block reduction: warp shfl max, then cross-warp via shared
    __shared__ float red[T_TILE][NTHREADS / 32];
    int lane = threadIdx.x & 31;
    int wid  = threadIdx.x >> 5;
    #pragma unroll
    for (int j = 0; j < T_TILE; j++) {
        float v = acc[j];
        #pragma unroll
        for (int o = 16; o > 0; o >>= 1)
            v = fmaxf(v, __shfl_xor_sync(0xffffffffu, v, o));
        if (lane == 0) red[j][wid] = v;
    }
    __syncthreads();
    if (threadIdx.x < T_TILE) {
        float v = red[threadIdx.x][0];
        #pragma unroll
        for (int w = 1; w < NTHREADS / 32; w++)
            v = fmaxf(v, red[threadIdx.x][w]);
        if (v > 0.0f)
            atomicMax(&g_acc[b * TTOT + tbase + threadIdx.x], __float_as_int(v));
    }

    // Fused final reduction: last block sums g_acc and writes the scalar
    __shared__ bool isLast;
    __threadfence();
    __syncthreads();
    if (threadIdx.x == 0) {
        unsigned int prev = atomicAdd(&g_done, 1u);
        isLast = (prev == (unsigned int)(NBLOCKS - 1));
    }
    __syncthreads();
    if (isLast) {
        __shared__ float sh[NTHREADS];
        float sum = 0.0f;
        for (int i = threadIdx.x; i < BB * TTOT; i += NTHREADS)
            sum += __int_as_float(g_acc[i]);
        sh[threadIdx.x] = sum;
        __syncthreads();
        for (int o = NTHREADS / 2; o > 0; o >>= 1) {
            if (threadIdx.x < o) sh[threadIdx.x] += sh[threadIdx.x + o];
            __syncthreads();
        }
        if (threadIdx.x == 0) out[0] = sh[0] / (float)(BB * TTOT);
    }
}

extern "C" void kernel_launch(void* const* d_in, const int* in_sizes, int n_in,
                              void* d_out, int out_size) {
    const float* outputs = (const float*)d_in[0];  // (8,100,3)
    const float* c2ws    = (const float*)d_in[1];  // (8,4,4)
    const float* ss      = (const float*)d_in[2];  // (8,)
    const float* means   = (const float*)d_in[3];  // (100000,3)
    const float* scales  = (const float*)d_in[4];  // (100000,3)
    float* out = (float*)d_out;

    prep_kernel<<<1, 256>>>(outputs, c2ws, ss);
    mask_kernel<<<(BB * NN + 255) / 256, 256>>>(means, scales);
    main_kernel<<<dim3(NSPLIT, TTOT / T_TILE, BB), NTHREADS>>>(out);
}

// round 5
// speedup vs baseline: 1.6998x; 1.6998x over previous
#include <cuda_runtime.h>

#define BB 8
#define TTOT 100
#define NN 100000
#define MARGIN_F 0.1f
#define THRESH_F 0.5f
#define T_TILE 20
#define NPAIR (T_TILE / 2)
#define NSPLIT 32
#define NTHREADS 128
#define NBLOCKS (NSPLIT * (TTOT / T_TILE) * BB)

typedef unsigned long long u64;

// Scratch (device globals; no allocation)
__device__ float4 g_retraj[BB * TTOT];   // (rx, ry, rz, r2)
__device__ float  g_lval[BB][3];
__device__ float  g_uval[BB][3];
__device__ float4 g_pts[BB * NN];        // (-2x, -2y, -2z, m2)
__device__ float  g_w[BB * NN];          // rad + MARGIN, or -1e30 if outside
__device__ int    g_acc[BB * TTOT];      // per-(b,t) max, float bits (>= 0)
__device__ unsigned int g_done;

__device__ __forceinline__ float fast_sqrt(float x) {
    float r;
    asm("sqrt.approx.f32 %0, %1;" : "=f"(r) : "f"(x));
    return r;
}
__device__ __forceinline__ u64 pack2(float lo, float hi) {
    u64 r;
    asm("mov.b64 %0, {%1, %2};" : "=l"(r) : "f"(lo), "f"(hi));
    return r;
}
__device__ __forceinline__ void unpack2(u64 v, float& lo, float& hi) {
    asm("mov.b64 {%0, %1}, %2;" : "=f"(lo), "=f"(hi) : "l"(v));
}
__device__ __forceinline__ u64 fma2(u64 a, u64 b, u64 c) {
    u64 d;
    asm("fma.rn.f32x2 %0, %1, %2, %3;" : "=l"(d) : "l"(a), "l"(b), "l"(c));
    return d;
}
__device__ __forceinline__ u64 add2(u64 a, u64 b) {
    u64 d;
    asm("add.rn.f32x2 %0, %1, %2;" : "=l"(d) : "l"(a), "l"(b));
    return d;
}

// Kernel 1: retrajs (+ r2), per-b bounds (shared-staged), zero accumulators
__global__ void prep_kernel(const float* __restrict__ outputs,
                            const float* __restrict__ c2ws,
                            const float* __restrict__ ss) {
    __shared__ float4 sh_r[BB * TTOT];   // 12.8 KB
    int tid = threadIdx.x;
    if (tid == 0) g_done = 0;
    for (int i = tid; i < BB * TTOT; i += blockDim.x) {
        int b = i / TTOT;
        float s = ss[b];
        const float* o = outputs + i * 3;
        const float* M = c2ws + b * 16;
        float o0 = o[0], o1 = o[1], o2 = o[2];
        float r[3];
        #pragma unroll
        for (int e = 0; e < 3; e++) {
            float a0 = M[e * 4 + 0] * s;
            float a1 = M[e * 4 + 1] * s;
            float a2 = M[e * 4 + 2] * s;
            r[e] = o0 * a0 + o1 * a1 + o2 * a2 + M[e * 4 + 3];
        }
        float r2 = r[0] * r[0] + r[1] * r[1] + r[2] * r[2];
        float4 v = make_float4(r[0], r[1], r[2], r2);
        g_retraj[i] = v;
        sh_r[i] = v;
        g_acc[i] = 0;
    }
    __syncthreads();
    if (tid < BB * 3) {
        int b = tid / 3, e = tid % 3;
        float thres = THRESH_F * ss[0];
        float mn = 1e30f, mx = -1e30f;
        for (int t = 0; t < TTOT; t++) {
            float4 rr = sh_r[b * TTOT + t];
            float v = (e == 0) ? rr.x : ((e == 1) ? rr.y : rr.z);
            mn = fminf(mn, v);
            mx = fmaxf(mx, v);
        }
        g_lval[b][e] = mn - thres;
        g_uval[b][e] = mx + thres;
    }
}

// Kernel 2: per-b point table, inside mask folded into w
__global__ void mask_kernel(const float* __restrict__ means,
                            const float* __restrict__ scales) {
    int i = blockIdx.x * blockDim.x + threadIdx.x;
    if (i >= BB * NN) return;
    int b = i / NN;
    int n = i - b * NN;
    float mx = means[n * 3 + 0];
    float my = means[n * 3 + 1];
    float mz = means[n * 3 + 2];
    float s0 = scales[n * 3 + 0];
    float s1 = scales[n * 3 + 1];
    float s2 = scales[n * 3 + 2];
    float rad = fmaxf(s0, fmaxf(s1, s2));
    bool inside = (mx >= g_lval[b][0]) & (mx <= g_uval[b][0]) &
                  (my >= g_lval[b][1]) & (my <= g_uval[b][1]) &
                  (mz >= g_lval[b][2]) & (mz <= g_uval[b][2]);
    float m2 = mx * mx + my * my + mz * mz;
    g_pts[i] = make_float4(-2.0f * mx, -2.0f * my, -2.0f * mz, m2);
    g_w[i] = inside ? (rad + MARGIN_F) : -1e30f;
}

// Kernel 3: main — packed f32x2 FMA chain, branch-free, fused final reduction
__global__ void __launch_bounds__(NTHREADS) main_kernel(float* __restrict__ out) {
    int b  = blockIdx.z;
    int tt = blockIdx.y;
    int s  = blockIdx.x;
    int tbase = tt * T_TILE;

    u64 rx2[NPAIR], ry2[NPAIR], rz2[NPAIR], C2[NPAIR];
    float acc[T_TILE];
    #pragma unroll
    for (int j = 0; j < NPAIR; j++) {
        float4 ra = g_retraj[b * TTOT + tbase + 2 * j];
        float4 rb = g_retraj[b * TTOT + tbase + 2 * j + 1];
        rx2[j] = pack2(ra.x, rb.x);
        ry2[j] = pack2(ra.y, rb.y);
        rz2[j] = pack2(ra.z, rb.z);
        C2[j]  = pack2(ra.w, rb.w);
        acc[2 * j] = 0.0f;
        acc[2 * j + 1] = 0.0f;
    }

    const float4* __restrict__ pts = g_pts + (size_t)b * NN;
    const float*  __restrict__ wv  = g_w  + (size_t)b * NN;
    const int chunk = NN / NSPLIT;
    int n0 = s * chunk;
    int n1 = n0 + chunk;

    #pragma unroll 2
    for (int n = n0 + threadIdx.x; n < n1; n += NTHREADS) {
        float4 p = pts[n];
        float  w = wv[n];
        u64 px2 = pack2(p.x, p.x);
        u64 py2 = pack2(p.y, p.y);
        u64 pz2 = pack2(p.z, p.z);
        u64 pm2 = pack2(p.w, p.w);
        #pragma unroll
        for (int j = 0; j < NPAIR; j++) {
            u64 d2p = add2(C2[j], pm2);
            d2p = fma2(px2, rx2[j], d2p);
            d2p = fma2(py2, ry2[j], d2p);
            d2p = fma2(pz2, rz2[j], d2p);
            float da, db;
            unpack2(d2p, da, db);
            da = fmaxf(da, 0.0f);
            db = fmaxf(db, 0.0f);
            acc[2 * j]     = fmaxf(acc[2 * j],     w - fast_sqrt(da));
            acc[2 * j + 1] = fmaxf(acc[2 * j + 1], w - fast_sqrt(db));
        }
    }

    // Block reduction: warp shfl max, then cross-warp via shared
    __shared__ float red[T_TILE][NTHREADS / 32];
    int lane = threadIdx.x & 31;
    int wid  = threadIdx.x >> 5;
    #pragma unroll
    for (int j = 0; j < T_TILE; j++) {
        float v = acc[j];
        #pragma unroll
        for (int o = 16; o > 0; o >>= 1)
            v = fmaxf(v, __shfl_xor_sync(0xffffffffu, v, o));
        if (lane == 0) red[j][wid] = v;
    }
    __syncthreads();
    if (threadIdx.x < T_TILE) {
        float v = red[threadIdx.x][0];
        #pragma unroll
        for (int w = 1; w < NTHREADS / 32; w++)
            v = fmaxf(v, red[threadIdx.x][w]);
        if (v > 0.0f)
            atomicMax(&g_acc[b * TTOT + tbase + threadIdx.x], __float_as_int(v));
    }

    // Fused final reduction: last block sums g_acc and writes the scalar
    __shared__ bool isLast;
    __threadfence();
    __syncthreads();
    if (threadIdx.x == 0) {
        unsigned int prev = atomicAdd(&g_done, 1u);
        isLast = (prev == (unsigned int)(NBLOCKS - 1));
    }
    __syncthreads();
    if (isLast) {
        __shared__ float sh[NTHREADS];
        float sum = 0.0f;
        for (int i = threadIdx.x; i < BB * TTOT; i += NTHREADS)
            sum += __int_as_float(g_acc[i]);
        sh[threadIdx.x] = sum;
        __syncthreads();
        for (int o = NTHREADS / 2; o > 0; o >>= 1) {
            if (threadIdx.x < o) sh[threadIdx.x] += sh[threadIdx.x + o];
            __syncthreads();
        }
        if (threadIdx.x == 0) out[0] = sh[0] / (float)(BB * TTOT);
    }
}

extern "C" void kernel_launch(void* const* d_in, const int* in_sizes, int n_in,
                              void* d_out, int out_size) {
    const float* outputs = (const float*)d_in[0];  // (8,100,3)
    const float* c2ws    = (const float*)d_in[1];  // (8,4,4)
    const float* ss      = (const float*)d_in[2];  // (8,)
    const float* means   = (const float*)d_in[3];  // (100000,3)
    const float* scales  = (const float*)d_in[4];  // (100000,3)
    float* out = (float*)d_out;

    prep_kernel<<<1, 256>>>(outputs, c2ws, ss);
    mask_kernel<<<(BB * NN + 255) / 256, 256>>>(means, scales);
    main_kernel<<<dim3(NSPLIT, TTOT / T_TILE, BB), NTHREADS>>>(out);
}

// round 6
// speedup vs baseline: 2.0017x; 1.1777x over previous
#include <cuda_runtime.h>

#define BB 8
#define TTOT 100
#define NN 100000
#define MARGIN_F 0.1f
#define THRESH_F 0.5f
#define T_TILE 10
#define NSPLIT 32
#define NTHREADS 256
#define NBLOCKS (NSPLIT * (TTOT / T_TILE) * BB)

// Scratch (device globals; no allocation)
__device__ float4 g_retraj[BB * TTOT];   // (rx, ry, rz, r2)
__device__ float  g_lval[BB][3];
__device__ float  g_uval[BB][3];
__device__ float4 g_pts[NN];             // (-2x, -2y, -2z, m2)  b-independent
__device__ float  g_w[BB * NN];          // rad + MARGIN, or -1e30 if outside
__device__ int    g_acc[BB * TTOT];      // per-(b,t) max, float bits (>= 0)
__device__ unsigned int g_done;

__device__ __forceinline__ float fast_sqrt(float x) {
    float r;
    asm("sqrt.approx.f32 %0, %1;" : "=f"(r) : "f"(x));
    return r;
}

// Kernel 1: retrajs (+ r2), per-b bounds, zero accumulators. Block (128, 8).
__global__ void prep_kernel(const float* __restrict__ outputs,
                            const float* __restrict__ c2ws,
                            const float* __restrict__ ss) {
    __shared__ float4 sh_r[BB][TTOT];
    int t = threadIdx.x;          // 0..127 (active < 100)
    int b = threadIdx.y;          // 0..7
    int flat = threadIdx.y * blockDim.x + threadIdx.x;
    if (flat == 0) g_done = 0;
    if (flat < BB * TTOT) g_acc[flat] = 0;

    if (t < TTOT) {
        int i = b * TTOT + t;
        float s = ss[b];
        const float* o = outputs + i * 3;
        const float* M = c2ws + b * 16;
        float o0 = o[0], o1 = o[1], o2 = o[2];
        float r[3];
        #pragma unroll
        for (int e = 0; e < 3; e++) {
            float a0 = M[e * 4 + 0] * s;
            float a1 = M[e * 4 + 1] * s;
            float a2 = M[e * 4 + 2] * s;
            r[e] = o0 * a0 + o1 * a1 + o2 * a2 + M[e * 4 + 3];
        }
        float r2 = r[0] * r[0] + r[1] * r[1] + r[2] * r[2];
        float4 v = make_float4(r[0], r[1], r[2], r2);
        g_retraj[i] = v;
        sh_r[b][t] = v;
    }
    __syncthreads();
    if (flat < BB * 3) {
        int bb = flat / 3, e = flat - bb * 3;
        float thres = THRESH_F * ss[0];
        float mn = 1e30f, mx = -1e30f;
        #pragma unroll 4
        for (int tt = 0; tt < TTOT; tt++) {
            float4 rr = sh_r[bb][tt];
            float v = (e == 0) ? rr.x : ((e == 1) ? rr.y : rr.z);
            mn = fminf(mn, v);
            mx = fmaxf(mx, v);
        }
        g_lval[bb][e] = mn - thres;
        g_uval[bb][e] = mx + thres;
    }
}

// Kernel 2: point table once; per-b w with inside mask folded in
__global__ void mask_kernel(const float* __restrict__ means,
                            const float* __restrict__ scales) {
    int n = blockIdx.x * blockDim.x + threadIdx.x;
    if (n >= NN) return;
    float mx = means[n * 3 + 0];
    float my = means[n * 3 + 1];
    float mz = means[n * 3 + 2];
    float s0 = scales[n * 3 + 0];
    float s1 = scales[n * 3 + 1];
    float s2 = scales[n * 3 + 2];
    float rad = fmaxf(s0, fmaxf(s1, s2));
    float m2 = mx * mx + my * my + mz * mz;
    g_pts[n] = make_float4(-2.0f * mx, -2.0f * my, -2.0f * mz, m2);
    float wbase = rad + MARGIN_F;
    #pragma unroll
    for (int b = 0; b < BB; b++) {
        bool inside = (mx >= g_lval[b][0]) & (mx <= g_uval[b][0]) &
                      (my >= g_lval[b][1]) & (my <= g_uval[b][1]) &
                      (mz >= g_lval[b][2]) & (mz <= g_uval[b][2]);
        g_w[b * NN + n] = inside ? wbase : -1e30f;
    }
}

// Kernel 3: main — scalar dot-form eval, branch-free, fused final reduction
__global__ void __launch_bounds__(NTHREADS) main_kernel(float* __restrict__ out) {
    int b  = blockIdx.z;
    int tt = blockIdx.y;
    int s  = blockIdx.x;
    int tbase = tt * T_TILE;

    float rx[T_TILE], ry[T_TILE], rz[T_TILE], C[T_TILE], acc[T_TILE];
    #pragma unroll
    for (int j = 0; j < T_TILE; j++) {
        float4 r = g_retraj[b * TTOT + tbase + j];
        rx[j] = r.x; ry[j] = r.y; rz[j] = r.z; C[j] = r.w;
        acc[j] = 0.0f;
    }

    const float4* __restrict__ pts = g_pts;
    const float*  __restrict__ wv  = g_w + (size_t)b * NN;
    const int chunk = NN / NSPLIT;
    int n0 = s * chunk;
    int n1 = (s == NSPLIT - 1) ? NN : (n0 + chunk);

    #pragma unroll 2
    for (int n = n0 + threadIdx.x; n < n1; n += NTHREADS) {
        float4 p = pts[n];
        float  w = wv[n];
        #pragma unroll
        for (int j = 0; j < T_TILE; j++) {
            float d2 = C[j] + p.w;
            d2 = fmaf(p.x, rx[j], d2);
            d2 = fmaf(p.y, ry[j], d2);
            d2 = fmaf(p.z, rz[j], d2);
            d2 = fmaxf(d2, 0.0f);
            float v = w - fast_sqrt(d2);
            acc[j] = fmaxf(acc[j], v);
        }
    }

    // Block reduction: warp shfl max, then cross-warp via shared
    __shared__ float red[T_TILE][NTHREADS / 32];
    int lane = threadIdx.x & 31;
    int wid  = threadIdx.x >> 5;
    #pragma unroll
    for (int j = 0; j < T_TILE; j++) {
        float v = acc[j];
        #pragma unroll
        for (int o = 16; o > 0; o >>= 1)
            v = fmaxf(v, __shfl_xor_sync(0xffffffffu, v, o));
        if (lane == 0) red[j][wid] = v;
    }
    __syncthreads();
    if (threadIdx.x < T_TILE) {
        float v = red[threadIdx.x][0];
        #pragma unroll
        for (int w = 1; w < NTHREADS / 32; w++)
            v = fmaxf(v, red[threadIdx.x][w]);
        if (v > 0.0f)
            atomicMax(&g_acc[b * TTOT + tbase + threadIdx.x], __float_as_int(v));
    }

    // Fused final reduction: last block sums g_acc and writes the scalar
    __shared__ bool isLast;
    __threadfence();
    __syncthreads();
    if (threadIdx.x == 0) {
        unsigned int prev = atomicAdd(&g_done, 1u);
        isLast = (prev == (unsigned int)(NBLOCKS - 1));
    }
    __syncthreads();
    if (isLast) {
        __shared__ float sh[NTHREADS];
        float sum = 0.0f;
        for (int i = threadIdx.x; i < BB * TTOT; i += NTHREADS)
            sum += __int_as_float(g_acc[i]);
        sh[threadIdx.x] = sum;
        __syncthreads();
        for (int o = NTHREADS / 2; o > 0; o >>= 1) {
            if (threadIdx.x < o) sh[threadIdx.x] += sh[threadIdx.x + o];
            __syncthreads();
        }
        if (threadIdx.x == 0) out[0] = sh[0] / (float)(BB * TTOT);
    }
}

extern "C" void kernel_launch(void* const* d_in, const int* in_sizes, int n_in,
                              void* d_out, int out_size) {
    const float* outputs = (const float*)d_in[0];  // (8,100,3)
    const float* c2ws    = (const float*)d_in[1];  // (8,4,4)
    const float* ss      = (const float*)d_in[2];  // (8,)
    const float* means   = (const float*)d_in[3];  // (100000,3)
    const float* scales  = (const float*)d_in[4];  // (100000,3)
    float* out = (float*)d_out;

    prep_kernel<<<1, dim3(128, 8)>>>(outputs, c2ws, ss);
    mask_kernel<<<(NN + 255) / 256, 256>>>(means, scales);
    main_kernel<<<dim3(NSPLIT, TTOT / T_TILE, BB), NTHREADS>>>(out);
}